// round 8
// baseline (speedup 1.0000x reference)
#include <cuda_runtime.h>

#define ITEMS 32
#define BLOCK 224
#define CHUNK (ITEMS * BLOCK)   // 7168 -> G=586, one wave @4 CTA/SM (guaranteed co-resident)
#define NWARP (BLOCK / 32)      // 7
#define MAXBLKS 1024

__device__ float2 g_agg[MAXBLKS];   // per-block zero-state end state
__device__ int    g_bar;            // grid barrier counter (zeroed by ng_init each replay)

// Affine map s' = M s + v, M lower-triangular [[m00,0],[m10,m11]]
struct Aff { float m00, m10, m11, v0, v1; };

__device__ __forceinline__ Aff aff_combine(const Aff& B, const Aff& A) {
    Aff r;
    r.m00 = B.m00 * A.m00;
    r.m10 = fmaf(B.m10, A.m00, B.m11 * A.m10);
    r.m11 = B.m11 * A.m11;
    r.v0  = fmaf(B.m00, A.v0, B.v0);
    r.v1  = fmaf(B.m10, A.v0, fmaf(B.m11, A.v1, B.v1));
    return r;
}

__device__ __forceinline__ Aff aff_shfl_up(const Aff& a, int d) {
    Aff r;
    r.m00 = __shfl_up_sync(0xffffffffu, a.m00, d);
    r.m10 = __shfl_up_sync(0xffffffffu, a.m10, d);
    r.m11 = __shfl_up_sync(0xffffffffu, a.m11, d);
    r.v0  = __shfl_up_sync(0xffffffffu, a.v0,  d);
    r.v1  = __shfl_up_sync(0xffffffffu, a.v1,  d);
    return r;
}

__device__ __forceinline__ void get_params(const float* __restrict__ p,
                                           float& c1, float& c2,
                                           float& attack, float& decay, float& gain) {
    attack = fmaxf(p[0], 1e-7f);
    decay  = fmaxf(p[1], 1e-7f);
    c1 = fminf(fmaxf(p[2], 1e-7f), 0.99f);   // lowpass
    c2 = fminf(fmaxf(p[3], 1e-7f), 0.99f);   // highpass
    gain = fmaxf(p[4], 1e-7f);
}

__device__ __forceinline__ void mat_mul(float& c00, float& c10, float& c11,
                                        float a00, float a10, float a11,
                                        float b00, float b10, float b11) {
    c00 = a00 * b00;
    c10 = fmaf(a10, b00, a11 * b10);
    c11 = a11 * b11;
}

__device__ __forceinline__ void mat_sq_k(float& m00, float& m10, float& m11, int k) {
    #pragma unroll 1
    for (int i = 0; i < k; i++) {
        float n00 = m00 * m00;
        float n10 = m10 * (m00 + m11);
        float n11 = m11 * m11;
        m00 = n00; m10 = n10; m11 = n11;
    }
}

// ---------------------------------------------------------------------------
__global__ void ng_init() {
    if (threadIdx.x == 0 && blockIdx.x == 0) g_bar = 0;
}

// ---------------------------------------------------------------------------
// Fused: phase 1 (scan + publish aggregate), grid barrier, phase 2
// (lookback + seeded replay + envelope + store).
// ---------------------------------------------------------------------------
__global__ void __launch_bounds__(BLOCK, 4)
ng_fused(const float* __restrict__ params, const float* __restrict__ x,
         float* __restrict__ out, int n, int G) {
    float c1, c2, at, de, g;
    get_params(params, c1, c2, at, de, g);
    const float b1 = 1.0f - c1;
    const float dcoef = c2 * (c1 - 1.0f);
    const float bb = c2 * b1;

    const int tid  = threadIdx.x;
    const int bid  = blockIdx.x;
    const int lane = tid & 31, wid = tid >> 5;
    const long base = (long)bid * CHUNK + (long)tid * ITEMS;
    const bool full = (base + ITEMS) <= n;

    __shared__ Aff    wtot[NWARP];
    __shared__ Aff    pre[NWARP];     // exclusive warp-prefix affines
    __shared__ float  ACsh[3];        // block-total matrix = A^CHUNK
    __shared__ float2 wred[NWARP];

    // ================= Phase 1 =================
    {
        float xv[ITEMS];
        if (full) {
            const float4* xp = (const float4*)(x + base);
            #pragma unroll
            for (int k = 0; k < ITEMS / 4; k++) {
                float4 v = xp[k];
                xv[4*k+0] = v.x; xv[4*k+1] = v.y; xv[4*k+2] = v.z; xv[4*k+3] = v.w;
            }
        } else {
            #pragma unroll
            for (int j = 0; j < ITEMS; j++)
                xv[j] = (base + j < n) ? x[base + j] : 0.0f;
        }

        // stride-4 zero-state sweep (only end state needed)
        const float A2_00 = c1 * c1, A2_10 = dcoef * (c1 + c2), A2_11 = c2 * c2;
        const float A4_00 = A2_00 * A2_00, A4_10 = A2_10 * (A2_00 + A2_11), A4_11 = A2_11 * A2_11;
        const float q0x = b1,       q0y = bb;
        const float q1x = c1 * q0x, q1y = fmaf(dcoef, q0x, c2 * q0y);
        const float q2x = c1 * q1x, q2y = fmaf(dcoef, q1x, c2 * q1y);
        const float q3x = c1 * q2x, q3y = fmaf(dcoef, q2x, c2 * q2y);

        float y1 = 0.0f, y2 = 0.0f;
        #pragma unroll
        for (int k = 0; k < ITEMS / 4; k++) {
            float xa = xv[4*k+0], xb = xv[4*k+1], xc = xv[4*k+2], xd = xv[4*k+3];
            float u0 = fmaf(q2x, xb, q3x * xa) + fmaf(q0x, xd, q1x * xc);
            float u1 = fmaf(q2y, xb, q3y * xa) + fmaf(q0y, xd, q1y * xc);
            float y1n = fmaf(A4_00, y1, u0);
            y2 = fmaf(A4_10, y1, fmaf(A4_11, y2, u1));
            y1 = y1n;
        }

        // A^32 segment matrix
        float m00 = c1, m10 = dcoef, m11 = c2;
        mat_sq_k(m00, m10, m11, 5);
        Aff a = {m00, m10, m11, y1, y2};
        #pragma unroll
        for (int dd = 1; dd < 32; dd <<= 1) {
            Aff o = aff_shfl_up(a, dd);
            if (lane >= dd) a = aff_combine(a, o);
        }
        Aff exl = aff_shfl_up(a, 1);
        if (lane == 0) { exl.m00 = 1.f; exl.m10 = 0.f; exl.m11 = 1.f; exl.v0 = 0.f; exl.v1 = 0.f; }

        if (lane == 31) wtot[wid] = a;
        __syncthreads();
        if (tid == 0) {
            Aff p = {1.f, 0.f, 1.f, 0.f, 0.f};
            #pragma unroll
            for (int w = 0; w < NWARP; w++) { pre[w] = p; p = aff_combine(wtot[w], p); }
            g_agg[bid] = make_float2(p.v0, p.v1);
            ACsh[0] = p.m00; ACsh[1] = p.m10; ACsh[2] = p.m11;
        }
        __syncthreads();

        // thread's block-exclusive affine E (matrix = A^(32*tid), vector = excl state)
        Aff E = aff_combine(exl, pre[wid]);

        // ---- grid barrier (all-arrive, then proceed) ----
        __threadfence();
        __syncthreads();
        if (tid == 0) {
            asm volatile("red.release.gpu.global.add.s32 [%0], 1;" :: "l"(&g_bar) : "memory");
            int v;
            do {
                asm volatile("ld.acquire.gpu.global.b32 %0, [%1];" : "=r"(v) : "l"(&g_bar) : "memory");
            } while (v < G);
        }
        __syncthreads();

        // ================= Phase 2 =================
        // A_C = A^CHUNK from shared; Ml = A_C^tid (8-bit chain), S = A_C^224
        float p00 = ACsh[0], p10 = ACsh[1], p11 = ACsh[2];
        float Ml00 = 1.0f, Ml10 = 0.0f, Ml11 = 1.0f;
        float C500 = 1.f, C510 = 0.f, C511 = 1.f;
        float C600 = 1.f, C610 = 0.f, C611 = 1.f;
        float C700 = 1.f, C710 = 0.f, C711 = 1.f;
        #pragma unroll
        for (int b = 0; b < 8; b++) {
            if (b == 5) { C500 = p00; C510 = p10; C511 = p11; }
            if (b == 6) { C600 = p00; C610 = p10; C611 = p11; }
            if (b == 7) { C700 = p00; C710 = p10; C711 = p11; }
            if ((tid >> b) & 1) {
                float t00, t10, t11;
                mat_mul(t00, t10, t11, Ml00, Ml10, Ml11, p00, p10, p11);
                Ml00 = t00; Ml10 = t10; Ml11 = t11;
            }
            float q00, q10, q11;
            mat_mul(q00, q10, q11, p00, p10, p11, p00, p10, p11);
            p00 = q00; p10 = q10; p11 = q11;
        }
        float S00, S10, S11, T00, T10, T11;
        mat_mul(T00, T10, T11, C500, C510, C511, C600, C610, C611);
        mat_mul(S00, S10, S11, T00, T10, T11, C700, C710, C711);   // A_C^224

        // lookback: s_in = sum_{dd<bid} A_C^dd * agg[bid-1-dd]
        float r0 = 0.0f, r1 = 0.0f;
        for (int dd = tid; dd < bid; dd += BLOCK) {
            float2 v = __ldcg(&g_agg[bid - 1 - dd]);
            r0 = fmaf(Ml00, v.x, r0);
            r1 = fmaf(Ml10, v.x, fmaf(Ml11, v.y, r1));
            float t00, t10, t11;
            mat_mul(t00, t10, t11, Ml00, Ml10, Ml11, S00, S10, S11);
            Ml00 = t00; Ml10 = t10; Ml11 = t11;
        }
        #pragma unroll
        for (int dd = 16; dd > 0; dd >>= 1) {
            r0 += __shfl_xor_sync(0xffffffffu, r0, dd);
            r1 += __shfl_xor_sync(0xffffffffu, r1, dd);
        }
        if (lane == 0) wred[wid] = make_float2(r0, r1);
        __syncthreads();
        float sinx = 0.0f, siny = 0.0f;
        #pragma unroll
        for (int w = 0; w < NWARP; w++) { sinx += wred[w].x; siny += wred[w].y; }

        // thread seed: s0 = E.M * s_in + E.v
        y1 = fmaf(E.m00, sinx, E.v0);
        y2 = fmaf(E.m10, sinx, fmaf(E.m11, siny, E.v1));

        // envelope (geometric sequences)
        const float inv_n1 = 1.0f / (float)(n - 1);
        const float k1 = 1.0f / de;
        const float k2 = 1.0f / at + k1;
        const float t0 = (float)base * inv_n1;
        float e1 = g * __expf(-t0 * k1);
        float e2 = g * __expf(-t0 * k2);
        const float r1c = __expf(-inv_n1 * k1);
        const float r2c = __expf(-inv_n1 * k2);

        // reload x (L1/L2-resident from phase 1), replay, store
        if (full) {
            const float4* xp = (const float4*)(x + base);
            float4* op = (float4*)(out + base);
            #pragma unroll
            for (int k = 0; k < ITEMS / 4; k++) {
                float4 v = xp[k];
                float4 o;
                #pragma unroll
                for (int q = 0; q < 4; q++) {
                    float xn = (q == 0) ? v.x : (q == 1) ? v.y : (q == 2) ? v.z : v.w;
                    float y1n = fmaf(c1, y1, b1 * xn);
                    y2 = c2 * (y2 + (y1n - y1));
                    y1 = y1n;
                    float val = y2 * (e1 - e2);
                    e1 *= r1c; e2 *= r2c;
                    if (q == 0) o.x = val; else if (q == 1) o.y = val;
                    else if (q == 2) o.z = val; else o.w = val;
                }
                op[k] = o;
            }
        } else {
            #pragma unroll
            for (int j = 0; j < ITEMS; j++) {
                float xn = (base + j < n) ? x[base + j] : 0.0f;
                float y1n = fmaf(c1, y1, b1 * xn);
                y2 = c2 * (y2 + (y1n - y1));
                y1 = y1n;
                float val = y2 * (e1 - e2);
                e1 *= r1c; e2 *= r2c;
                if (base + j < n) out[base + j] = val;
            }
        }
    }
}

// ---------------------------------------------------------------------------
extern "C" void kernel_launch(void* const* d_in, const int* in_sizes, int n_in,
                              void* d_out, int out_size) {
    int i_par = 0, i_noise = 1;
    if (n_in >= 2 && in_sizes[0] > in_sizes[1]) { i_par = 1; i_noise = 0; }
    const float* params = (const float*)d_in[i_par];
    const float* noise  = (const float*)d_in[i_noise];
    float* out = (float*)d_out;
    const int n = in_sizes[i_noise];
    int G = (n + CHUNK - 1) / CHUNK;   // n = 2^22 -> G = 586 <= 592 co-resident capacity

    ng_init<<<1, 32>>>();
    ng_fused<<<G, BLOCK>>>(params, noise, out, n, G);
}

// round 9
// speedup vs baseline: 1.3570x; 1.3570x over previous
#include <cuda_runtime.h>

#define ITEMS 28
#define BLOCK 256
#define CHUNK (ITEMS * BLOCK)   // 7168 -> G=586, one wave @4 CTA/SM (1024 thr, 64-reg cap)
#define NWARP (BLOCK / 32)      // 8
#define MAXBLKS 1024
#define MAXTHR  (MAXBLKS * BLOCK)

__device__ float2 g_agg[MAXBLKS];   // per-block zero-state end state
__device__ float4 g_thrM[MAXTHR];   // per-thread exclusive matrix {m00,m10,m11,-}
__device__ float2 g_thrV[MAXTHR];   // per-thread exclusive zero-state vector

__device__ __forceinline__ void get_params(const float* __restrict__ p,
                                           float& c1, float& c2,
                                           float& attack, float& decay, float& gain) {
    attack = fmaxf(p[0], 1e-7f);
    decay  = fmaxf(p[1], 1e-7f);
    c1 = fminf(fmaxf(p[2], 1e-7f), 0.99f);   // lowpass
    c2 = fminf(fmaxf(p[3], 1e-7f), 0.99f);   // highpass
    gain = fmaxf(p[4], 1e-7f);
}

__device__ __forceinline__ void mat_mul(float& c00, float& c10, float& c11,
                                        float a00, float a10, float a11,
                                        float b00, float b10, float b11) {
    c00 = a00 * b00;
    c10 = fmaf(a10, b00, a11 * b10);
    c11 = a11 * b11;
}

__device__ __forceinline__ void mat_sq(float& m00, float& m10, float& m11) {
    float n00 = m00 * m00;
    float n10 = m10 * (m00 + m11);
    float n11 = m11 * m11;
    m00 = n00; m10 = n10; m11 = n11;
}

// P = A^28 (binary 11100) from A, 5 squarings + 3 muls
__device__ __forceinline__ void mat_pow28(float a00, float a10, float a11,
                                          float& M00, float& M10, float& M11) {
    M00 = 1.0f; M10 = 0.0f; M11 = 1.0f;
    float p00 = a00, p10 = a10, p11 = a11;
    #pragma unroll
    for (int b = 0; b < 5; b++) {
        if ((28 >> b) & 1) {
            float t00, t10, t11;
            mat_mul(t00, t10, t11, M00, M10, M11, p00, p10, p11);
            M00 = t00; M10 = t10; M11 = t11;
        }
        mat_sq(p00, p10, p11);
    }
}

// ---------------------------------------------------------------------------
// Pass 1: stride-4 sweep; vector-only KS scan (known constant matrices);
// publish per-thread exclusive affine (E.m, E.v) + block aggregate.
// ---------------------------------------------------------------------------
__global__ void __launch_bounds__(BLOCK, 4)
ng_pass1(const float* __restrict__ params, const float* __restrict__ x, int n) {
    float c1, c2, at, de, g;
    get_params(params, c1, c2, at, de, g);
    const float b1 = 1.0f - c1;
    const float dcoef = c2 * (c1 - 1.0f);
    const float bb = c2 * b1;

    const int tid = threadIdx.x;
    const int bid = blockIdx.x;
    const int lane = tid & 31, wid = tid >> 5;
    const long base = (long)bid * CHUNK + (long)tid * ITEMS;

    float xv[ITEMS];
    if (base + ITEMS <= n) {
        const float4* xp = (const float4*)(x + base);
        #pragma unroll
        for (int k = 0; k < ITEMS / 4; k++) {
            float4 v = xp[k];
            xv[4*k+0] = v.x; xv[4*k+1] = v.y; xv[4*k+2] = v.z; xv[4*k+3] = v.w;
        }
    } else {
        #pragma unroll
        for (int j = 0; j < ITEMS; j++)
            xv[j] = (base + j < n) ? x[base + j] : 0.0f;
    }

    // stride-4 zero-state sweep (end state only)
    const float A2_00 = c1 * c1, A2_10 = dcoef * (c1 + c2), A2_11 = c2 * c2;
    const float A4_00 = A2_00 * A2_00, A4_10 = A2_10 * (A2_00 + A2_11), A4_11 = A2_11 * A2_11;
    const float q0x = b1,       q0y = bb;
    const float q1x = c1 * q0x, q1y = fmaf(dcoef, q0x, c2 * q0y);
    const float q2x = c1 * q1x, q2y = fmaf(dcoef, q1x, c2 * q1y);
    const float q3x = c1 * q2x, q3y = fmaf(dcoef, q2x, c2 * q2y);

    float v0 = 0.0f, v1 = 0.0f;
    #pragma unroll
    for (int k = 0; k < ITEMS / 4; k++) {
        float xa = xv[4*k+0], xb = xv[4*k+1], xc = xv[4*k+2], xd = xv[4*k+3];
        float u0 = fmaf(q2x, xb, q3x * xa) + fmaf(q0x, xd, q1x * xc);
        float u1 = fmaf(q2y, xb, q3y * xa) + fmaf(q0y, xd, q1y * xc);
        float v0n = fmaf(A4_00, v0, u0);
        v1 = fmaf(A4_10, v0, fmaf(A4_11, v1, u1));
        v0 = v0n;
    }

    // P = A^28
    float P00, P10, P11;
    mat_pow28(c1, dcoef, c2, P00, P10, P11);

    // Vector-only Kogge-Stone scan with constant round matrices P^(2^k).
    // Simultaneously build Mlane = P^lane from the same chain.
    float pk00 = P00, pk10 = P10, pk11 = P11;
    float Ml00 = 1.0f, Ml10 = 0.0f, Ml11 = 1.0f;
    #pragma unroll
    for (int k = 0; k < 5; k++) {
        int dd = 1 << k;
        float o0 = __shfl_up_sync(0xffffffffu, v0, dd);
        float o1 = __shfl_up_sync(0xffffffffu, v1, dd);
        if (lane >= dd) {
            v0 = fmaf(pk00, o0, v0);
            v1 = fmaf(pk10, o0, fmaf(pk11, o1, v1));
        }
        if ((lane >> k) & 1) {
            float t00, t10, t11;
            mat_mul(t00, t10, t11, Ml00, Ml10, Ml11, pk00, pk10, pk11);
            Ml00 = t00; Ml10 = t10; Ml11 = t11;
        }
        mat_sq(pk00, pk10, pk11);   // P^(2^(k+1))
    }
    // pk = P^32 (warp-total matrix)

    // warp-exclusive vector
    float ve0 = __shfl_up_sync(0xffffffffu, v0, 1);
    float ve1 = __shfl_up_sync(0xffffffffu, v1, 1);
    if (lane == 0) { ve0 = 0.0f; ve1 = 0.0f; }

    __shared__ float2 wtotv[NWARP];
    __shared__ float2 prev[NWARP];
    if (lane == 31) wtotv[wid] = make_float2(v0, v1);
    __syncthreads();
    if (tid == 0) {
        // block serial over 8 warps with constant matrix P^32 (= pk)
        float s0 = 0.0f, s1 = 0.0f;
        #pragma unroll
        for (int w = 0; w < NWARP; w++) {
            prev[w] = make_float2(s0, s1);
            float2 wv = wtotv[w];
            float ns0 = fmaf(pk00, s0, wv.x);
            s1 = fmaf(pk10, s0, fmaf(pk11, s1, wv.y));
            s0 = ns0;
        }
        g_agg[bid] = make_float2(s0, s1);
    }
    __syncthreads();

    // Mwid = (P^32)^wid  (3-bit chain over pk squarings)
    float Mw00 = 1.0f, Mw10 = 0.0f, Mw11 = 1.0f;
    float w00 = pk00, w10 = pk10, w11 = pk11;
    #pragma unroll
    for (int k = 0; k < 3; k++) {
        if ((wid >> k) & 1) {
            float t00, t10, t11;
            mat_mul(t00, t10, t11, Mw00, Mw10, Mw11, w00, w10, w11);
            Mw00 = t00; Mw10 = t10; Mw11 = t11;
        }
        mat_sq(w00, w10, w11);
    }

    // E.m = Mlane * Mwid (commuting powers); E.v = Mlane * prev[wid] + ve
    float Em00, Em10, Em11;
    mat_mul(Em00, Em10, Em11, Ml00, Ml10, Ml11, Mw00, Mw10, Mw11);
    float2 pv = prev[wid];
    float Ev0 = fmaf(Ml00, pv.x, ve0);
    float Ev1 = fmaf(Ml10, pv.x, fmaf(Ml11, pv.y, ve1));

    const int gid = bid * BLOCK + tid;
    g_thrM[gid] = make_float4(Em00, Em10, Em11, 0.0f);
    g_thrV[gid] = make_float2(Ev0, Ev1);
}

// ---------------------------------------------------------------------------
// Pass 3: load E, powering for lookback only, lookback, seed, replay, store.
// ---------------------------------------------------------------------------
__global__ void __launch_bounds__(BLOCK, 4)
ng_pass3(const float* __restrict__ params, const float* __restrict__ x,
         float* __restrict__ out, int n) {
    float c1, c2, at, de, g;
    get_params(params, c1, c2, at, de, g);
    const float b1 = 1.0f - c1;
    const float dcoef = c2 * (c1 - 1.0f);
    const float bb = c2 * b1;

    const int tid  = threadIdx.x;
    const int bid  = blockIdx.x;
    const int lane = tid & 31, wid = tid >> 5;
    const long base = (long)bid * CHUNK + (long)tid * ITEMS;
    const bool full = (base + ITEMS) <= n;

    // ---- issue loads early ----
    float xv[ITEMS];
    if (full) {
        const float4* xp = (const float4*)(x + base);
        #pragma unroll
        for (int k = 0; k < ITEMS / 4; k++) {
            float4 v = xp[k];
            xv[4*k+0] = v.x; xv[4*k+1] = v.y; xv[4*k+2] = v.z; xv[4*k+3] = v.w;
        }
    } else {
        #pragma unroll
        for (int j = 0; j < ITEMS; j++)
            xv[j] = (base + j < n) ? x[base + j] : 0.0f;
    }
    const int gid = bid * BLOCK + tid;
    float4 EM = __ldg(&g_thrM[gid]);
    float2 EV = __ldg(&g_thrV[gid]);

    // ---- powering for lookback: A_C = (A^28)^256; Ml = A_C^tid; S = A_C^256 ----
    float p00, p10, p11;
    mat_pow28(c1, dcoef, c2, p00, p10, p11);     // A^28
    #pragma unroll
    for (int k = 0; k < 8; k++) mat_sq(p00, p10, p11);   // A_C = A^7168
    float Ml00 = 1.0f, Ml10 = 0.0f, Ml11 = 1.0f;
    #pragma unroll
    for (int b = 0; b < 8; b++) {
        if ((tid >> b) & 1) {
            float t00, t10, t11;
            mat_mul(t00, t10, t11, Ml00, Ml10, Ml11, p00, p10, p11);
            Ml00 = t00; Ml10 = t10; Ml11 = t11;
        }
        mat_sq(p00, p10, p11);
    }
    // p = A_C^256 = S

    // ---- lookback: s_in = sum_{dd<bid} A_C^dd * agg[bid-1-dd] ----
    float r0 = 0.0f, r1 = 0.0f;
    for (int dd = tid; dd < bid; dd += BLOCK) {
        float2 v = __ldg(&g_agg[bid - 1 - dd]);
        r0 = fmaf(Ml00, v.x, r0);
        r1 = fmaf(Ml10, v.x, fmaf(Ml11, v.y, r1));
        float t00, t10, t11;
        mat_mul(t00, t10, t11, Ml00, Ml10, Ml11, p00, p10, p11);
        Ml00 = t00; Ml10 = t10; Ml11 = t11;
    }
    #pragma unroll
    for (int dd = 16; dd > 0; dd >>= 1) {
        r0 += __shfl_xor_sync(0xffffffffu, r0, dd);
        r1 += __shfl_xor_sync(0xffffffffu, r1, dd);
    }
    __shared__ float2 wred[NWARP];
    if (lane == 0) wred[wid] = make_float2(r0, r1);
    __syncthreads();
    float sinx = 0.0f, siny = 0.0f;
    #pragma unroll
    for (int w = 0; w < NWARP; w++) { sinx += wred[w].x; siny += wred[w].y; }

    // ---- seed: s0 = E.m * s_in + E.v ----
    float y1 = fmaf(EM.x, sinx, EV.x);
    float y2 = fmaf(EM.y, sinx, fmaf(EM.z, siny, EV.y));

    // ---- envelope (independent geometric chains) ----
    const float inv_n1 = 1.0f / (float)(n - 1);
    const float k1 = 1.0f / de;
    const float k2 = 1.0f / at + k1;
    const float t0 = (float)base * inv_n1;
    float e1 = g * __expf(-t0 * k1);
    float e2 = g * __expf(-t0 * k2);
    const float r1c = __expf(-inv_n1 * k1);
    const float r2c = __expf(-inv_n1 * k2);

    // ---- replay (expanded form: 1-FMA self-dependency per state) + store ----
    if (full) {
        float4* op = (float4*)(out + base);
        #pragma unroll
        for (int k = 0; k < ITEMS / 4; k++) {
            float4 o;
            #pragma unroll
            for (int q = 0; q < 4; q++) {
                float xn = xv[4*k + q];
                float t  = fmaf(dcoef, y1, bb * xn);   // off-chain
                y2 = fmaf(c2, y2, t);                  // 4-cyc chain
                y1 = fmaf(c1, y1, b1 * xn);            // 4-cyc chain
                float val = y2 * (e1 - e2);
                e1 *= r1c; e2 *= r2c;
                if (q == 0) o.x = val; else if (q == 1) o.y = val;
                else if (q == 2) o.z = val; else o.w = val;
            }
            op[k] = o;
        }
    } else {
        #pragma unroll
        for (int j = 0; j < ITEMS; j++) {
            float xn = xv[j];
            float t  = fmaf(dcoef, y1, bb * xn);
            y2 = fmaf(c2, y2, t);
            y1 = fmaf(c1, y1, b1 * xn);
            float val = y2 * (e1 - e2);
            e1 *= r1c; e2 *= r2c;
            if (base + j < n) out[base + j] = val;
        }
    }
}

// ---------------------------------------------------------------------------
extern "C" void kernel_launch(void* const* d_in, const int* in_sizes, int n_in,
                              void* d_out, int out_size) {
    int i_par = 0, i_noise = 1;
    if (n_in >= 2 && in_sizes[0] > in_sizes[1]) { i_par = 1; i_noise = 0; }
    const float* params = (const float*)d_in[i_par];
    const float* noise  = (const float*)d_in[i_noise];
    float* out = (float*)d_out;
    const int n = in_sizes[i_noise];
    int G = (n + CHUNK - 1) / CHUNK;
    if (G > MAXBLKS) G = MAXBLKS;  // n = 2^22 -> G = 586 (one wave @ 4 CTAs/SM)

    ng_pass1<<<G, BLOCK>>>(params, noise, n);
    ng_pass3<<<G, BLOCK>>>(params, noise, out, n);
}